// round 12
// baseline (speedup 1.0000x reference)
#include <cuda_runtime.h>
#include <cuda_bf16.h>

// WaveletTransform: 3-level low-pass pyramid on x[8,32,512,512] fp32.
// out = x, except per-channel:
//   out[0:256,0:256] = down2x(conv3x3(x[0:512,0:512]))        (level 0)
//   out[0:128,0:128] = down2x(conv3x3(level0 result[0:256]^2)) (level 1)
//   out[0: 64,0: 64] = down2x(conv3x3(level1 result[0:128]^2)) (level 2)
// conv = outer([.25,.5,.25],[.25,.5,.25]), zero-padded 'same', even-index
// downsample (center 2i,2j -> taps 2i-1..2i+1).
//
// R12: R11's 4-strip K23 raced (strip writes into out[0:128]^2 while
//      sibling strips of the same channel still read out[0:256]^2 for
//      level-1; rel_err 1.2e-4). Fix: strips of a channel form a CGA
//      cluster of 4; barrier.cluster between the read phase and the
//      write phase closes the hazard at exactly the right scope.
//      K1 unchanged (R3 shape, 78.6us local optimum).

#define BC_TOTAL (8 * 32)
#define H0 512
#define W0C 512

#define L1S 132                          // 128 + 4 floats pad
#define L1_ROWS 33

__device__ __forceinline__ float hfilt(float a, float b, float c) {
    return 0.25f * a + 0.5f * b + 0.25f * c;
}

// ---------------------------------------------------------------------------
// K1: fused identity copy + level-0 conv-down into top-left 256^2.
// grid (1,64,256), block 256.  (exact R3/R4 version)
// ---------------------------------------------------------------------------
__global__ void __launch_bounds__(256) k1_copy_down0(
    const float* __restrict__ x, float* __restrict__ out)
{
    const int j4   = threadIdx.x & 127;          // 0..127 (col/4)
    const int sub  = threadIdx.x >> 7;           // 0..1
    const int base = blockIdx.y * 8 + sub * 4;   // first of 4 rows
    const int bc   = blockIdx.z;

    const float* xp = x   + (size_t)bc * H0 * W0C;
    float*       op = out + (size_t)bc * H0 * W0C;

    if (base < 256 && j4 < 64) {
        #pragma unroll
        for (int it = 0; it < 4; it++) {
            const int i  = base + it;
            const int r0 = 2 * i - 1;
            float acc0 = 0.f, acc1 = 0.f, acc2 = 0.f, acc3 = 0.f;
            #pragma unroll
            for (int a = 0; a < 3; a++) {
                const int r = r0 + a;            // <= 511
                if (r < 0) continue;             // warp-uniform
                const float wr = (a == 1) ? 0.5f : 0.25f;
                const float* row = xp + (size_t)r * W0C;
                const float4* rv = reinterpret_cast<const float4*>(row) + 2 * j4;
                float4 p0 = rv[0];
                float4 p1 = rv[1];
                float left = __shfl_up_sync(0xFFFFFFFFu, p1.w, 1);
                if ((j4 & 31) == 0)
                    left = (j4 == 0) ? 0.f : row[8 * j4 - 1];
                acc0 += wr * hfilt(left, p0.x, p0.y);
                acc1 += wr * hfilt(p0.y, p0.z, p0.w);
                acc2 += wr * hfilt(p0.w, p1.x, p1.y);
                acc3 += wr * hfilt(p1.y, p1.z, p1.w);
            }
            *reinterpret_cast<float4*>(op + (size_t)i * W0C + 4 * j4) =
                make_float4(acc0, acc1, acc2, acc3);
        }
    } else {
        float4 v[4];
        #pragma unroll
        for (int it = 0; it < 4; it++)
            v[it] = *(reinterpret_cast<const float4*>(
                          xp + (size_t)(base + it) * W0C) + j4);
        #pragma unroll
        for (int it = 0; it < 4; it++)
            __stcs(reinterpret_cast<float4*>(
                       op + (size_t)(base + it) * W0C) + j4, v[it]);
    }
}

// ---------------------------------------------------------------------------
// K23s: strip version of fused levels 1+2, clustered per channel.
// grid (4, 256), block 256, cluster (4,1,1): blockIdx.x = strip k,
// blockIdx.y = channel. CTA (k, bc): smem holds level-1 rows
// 32k-1 .. 32k+31 (33 rows; r1 < 0 stored as zeros).
// barrier.cluster between phase 1 (reads of out[0:256]^2) and phase 2
// (writes into out[0:128]^2) closes the intra-channel RAW/WAR hazard.
// ---------------------------------------------------------------------------
__global__ void __launch_bounds__(256) __cluster_dims__(4, 1, 1)
k23_strip(float* __restrict__ out)
{
    __shared__ float l1[L1_ROWS * L1S];

    const int tid  = threadIdx.x;
    const int lane = tid & 31;
    const int wid  = tid >> 5;                  // 0..7
    const int k    = blockIdx.x;                // strip 0..3
    const int bc   = blockIdx.y;

    float* op = out + (size_t)bc * H0 * W0C;

    // ---- Phase 1: level-1 conv -> smem rows 0..32 (r1 = 32k-1+r_local) ----
    #pragma unroll
    for (int t = 0; t < 5; t++) {
        const int r_local = 8 * t + wid;        // 0..39; valid <= 32
        if (r_local <= 32) {
            const int r1 = 32 * k - 1 + r_local;   // -1..127
            float acc0 = 0.f, acc1 = 0.f, acc2 = 0.f, acc3 = 0.f;
            if (r1 >= 0) {                      // warp-uniform
                const int r0v = 2 * r1 - 1;
                #pragma unroll
                for (int a = 0; a < 3; a++) {
                    const int r = r0v + a;      // <= 255
                    if (r < 0) continue;        // warp-uniform
                    const float wr = (a == 1) ? 0.5f : 0.25f;
                    const float* row = op + (size_t)r * W0C;
                    const float4* rv =
                        reinterpret_cast<const float4*>(row) + 2 * lane;
                    float4 p0 = rv[0];
                    float4 p1 = rv[1];
                    float left = __shfl_up_sync(0xFFFFFFFFu, p1.w, 1);
                    if (lane == 0) left = 0.f;
                    acc0 += wr * hfilt(left, p0.x, p0.y);
                    acc1 += wr * hfilt(p0.y, p0.z, p0.w);
                    acc2 += wr * hfilt(p0.w, p1.x, p1.y);
                    acc3 += wr * hfilt(p1.y, p1.z, p1.w);
                }
            }
            *reinterpret_cast<float4*>(&l1[r_local * L1S + 4 * lane]) =
                make_float4(acc0, acc1, acc2, acc3);   // zeros when r1 < 0
        }
    }

    // ---- Cluster barrier: all strips of this channel done READING level-0
    //      before any strip WRITES into out[0:128]^2 (subset of read region).
    asm volatile("barrier.cluster.arrive.aligned;" ::: "memory");
    asm volatile("barrier.cluster.wait.aligned;"   ::: "memory");
    __syncthreads();   // order smem phase-1 stores vs phase-2 reads (CTA scope)

    // ---- Phase 2a: level-2 rows 16k..16k+15, one float4 per thread ----
    {
        const int i2l = tid >> 4;               // 0..15
        const int g   = tid & 15;               // float4 col group
        float acc0 = 0.f, acc1 = 0.f, acc2 = 0.f, acc3 = 0.f;
        #pragma unroll
        for (int a = 0; a < 3; a++) {
            const int loc = 2 * i2l + a;        // 0..31 (local row -1 = zeros)
            const float* row = &l1[loc * L1S];
            float4 p0 = *reinterpret_cast<const float4*>(row + 8 * g);
            float4 p1 = *reinterpret_cast<const float4*>(row + 8 * g + 4);
            const float wr = (a == 1) ? 0.5f : 0.25f;
            float left = __shfl_up_sync(0xFFFFFFFFu, p1.w, 1);
            if (g == 0) left = 0.f;
            acc0 += wr * hfilt(left, p0.x, p0.y);
            acc1 += wr * hfilt(p0.y, p0.z, p0.w);
            acc2 += wr * hfilt(p0.w, p1.x, p1.y);
            acc3 += wr * hfilt(p1.y, p1.z, p1.w);
        }
        *reinterpret_cast<float4*>(
            op + (size_t)(16 * k + i2l) * W0C + 4 * g) =
            make_float4(acc0, acc1, acc2, acc3);
    }

    // ---- Phase 2b: copy level-1 rows 32k..32k+31 outside inner 64^2 ----
    #pragma unroll
    for (int q = 0; q < 4; q++) {
        const int idx = tid + 256 * q;          // 0..1023
        const int row = idx >> 5;               // 0..31
        const int j4  = idx & 31;               // 0..31
        const int i   = 32 * k + row;           // 0..127
        if (i >= 64 || j4 >= 16) {
            float4 v = *reinterpret_cast<const float4*>(
                           &l1[(row + 1) * L1S + 4 * j4]);
            *reinterpret_cast<float4*>(op + (size_t)i * W0C + 4 * j4) = v;
        }
    }
}

extern "C" void kernel_launch(void* const* d_in, const int* in_sizes, int n_in,
                              void* d_out, int out_size)
{
    (void)in_sizes; (void)n_in; (void)out_size;
    const float* x = (const float*)d_in[0];
    float* out = (float*)d_out;

    k1_copy_down0<<<dim3(1, 64, BC_TOTAL), dim3(256)>>>(x, out);
    k23_strip    <<<dim3(4, BC_TOTAL), dim3(256)>>>(out);
}